// round 16
// baseline (speedup 1.0000x reference)
#include <cuda_runtime.h>
#include <cuda_fp16.h>
#include <math.h>
#include <stdint.h>

// Problem constants
#define Bc   8
#define Sc   512
#define Dc   1024
#define Hc   16
#define DHc  64
#define Mc   1024
#define DFc  4096
#define Vc   32000
#define Lc   6

typedef __half h16;

// ---------------------------------------------------------------------------
// Scratch (device globals)
// ---------------------------------------------------------------------------
__device__ float g_x[Bc * Sc * Dc];
__device__ float g_o[Bc * Sc * Dc];
__device__ h16 g_xh[Bc * Sc * Dc];
__device__ h16 g_qkvh[Bc * Sc * 3 * Dc];
__device__ h16 g_qh[Bc * Sc * Dc];
__device__ h16 g_kvh[Bc * Mc * 2 * Dc];
__device__ h16 g_ah[Bc * Sc * Dc];
__device__ h16 g_fh[Bc * Sc * DFc];
__device__ h16 g_eh[Bc * Mc * Dc];

#define WOFF_LAYER 16777216ull
#define WOFF_W1    8388608ull
#define WOFF_W2    12582912ull
#define EOFF       100663296ull
#define WTOTAL     133431296ull
__device__ h16 g_w[WTOTAL];

// ===========================================================================
// helpers
// ===========================================================================
__device__ __forceinline__ uint32_t smem_u32(const void* p) {
    uint32_t a;
    asm("{ .reg .u64 t; cvta.to.shared.u64 t, %1; cvt.u32.u64 %0, t; }"
        : "=r"(a) : "l"(p));
    return a;
}

__device__ __forceinline__ void mma_f16(float* d, const uint32_t* a, const uint32_t* b) {
    asm volatile(
        "mma.sync.aligned.m16n8k16.row.col.f32.f16.f16.f32 "
        "{%0,%1,%2,%3}, {%4,%5,%6,%7}, {%8,%9}, {%0,%1,%2,%3};"
        : "+f"(d[0]), "+f"(d[1]), "+f"(d[2]), "+f"(d[3])
        : "r"(a[0]), "r"(a[1]), "r"(a[2]), "r"(a[3]), "r"(b[0]), "r"(b[1]));
}

#define LDSM_X4(r, addr) \
    asm volatile("ldmatrix.sync.aligned.m8n8.x4.shared.b16 {%0,%1,%2,%3}, [%4];" \
        : "=r"((r)[0]), "=r"((r)[1]), "=r"((r)[2]), "=r"((r)[3]) : "r"(addr))

#define LDSM_X4T(r, addr) \
    asm volatile("ldmatrix.sync.aligned.m8n8.x4.trans.shared.b16 {%0,%1,%2,%3}, [%4];" \
        : "=r"((r)[0]), "=r"((r)[1]), "=r"((r)[2]), "=r"((r)[3]) : "r"(addr))

#define CP_ASYNC16(dst, src) \
    asm volatile("cp.async.cg.shared.global [%0], [%1], 16;" :: "r"(dst), "l"(src))
#define CP_COMMIT()  asm volatile("cp.async.commit_group;" ::: "memory")
#define CP_WAIT2()   asm volatile("cp.async.wait_group 2;" ::: "memory")
#define CP_WAIT1()   asm volatile("cp.async.wait_group 1;" ::: "memory")
#define CP_WAIT0()   asm volatile("cp.async.wait_group 0;" ::: "memory")

// ===========================================================================
// Conversion kernels — 2 launches total
// ===========================================================================
__global__ void convT_all(const float* __restrict__ Wq, const float* __restrict__ Wk,
                          const float* __restrict__ Wv, const float* __restrict__ Wo,
                          const float* __restrict__ Wqc, const float* __restrict__ Wkc,
                          const float* __restrict__ Wvc, const float* __restrict__ Woc,
                          const float* __restrict__ W1, const float* __restrict__ W2,
                          h16* __restrict__ dst)
{
    __shared__ float ts[32][33];
    const int z = blockIdx.z;
    const int t = blockIdx.x;

    const float* src;
    h16* out;
    int K, N, k0, n0;

    if (z < 48) {
        if (t >= 1024) return;
        const int layer = z >> 3;
        const int j     = z & 7;
        const float* srcs[8] = { Wq, Wk, Wv, Wo, Wqc, Wkc, Wvc, Woc };
        src = srcs[j] + (size_t)layer * Dc * Dc;
        out = dst + (size_t)layer * WOFF_LAYER + (size_t)j * 1048576;
        K = Dc; N = Dc;
        k0 = (t >> 5) * 32;
        n0 = (t & 31) * 32;
    } else if (z < 54) {
        const int layer = z - 48;
        src = W1 + (size_t)layer * Dc * DFc;
        out = dst + (size_t)layer * WOFF_LAYER + WOFF_W1;
        K = Dc; N = DFc;
        n0 = (t & 127) * 32;
        k0 = (t >> 7) * 32;
    } else {
        const int layer = z - 54;
        src = W2 + (size_t)layer * DFc * Dc;
        out = dst + (size_t)layer * WOFF_LAYER + WOFF_W2;
        K = DFc; N = Dc;
        n0 = (t & 31) * 32;
        k0 = (t >> 5) * 32;
    }

    const int tx = threadIdx.x, ty = threadIdx.y;
#pragma unroll
    for (int j = 0; j < 4; j++)
        ts[ty + j * 8][tx] = src[(size_t)(k0 + ty + j * 8) * N + n0 + tx];
    __syncthreads();
#pragma unroll
    for (int j = 0; j < 4; j++) {
        int n = ty + j * 8;
        out[(size_t)(n0 + n) * K + k0 + tx] = __float2half(ts[tx][n]);
    }
}

__global__ void conv_all(const float4* __restrict__ outemb, const float4* __restrict__ enc,
                         __half2* __restrict__ w_out, __half2* __restrict__ e_out)
{
    const int z = blockIdx.z;
    if (z == 1 && blockIdx.x >= (Bc * Mc)) return;
    const float4* src = (z == 0) ? outemb : enc;
    __half2* out = (z == 0) ? w_out : e_out;

    size_t i = (size_t)blockIdx.x * blockDim.x + threadIdx.x;
    float4 v = src[i];
    out[i * 2]     = __floats2half2_rn(v.x, v.y);
    out[i * 2 + 1] = __floats2half2_rn(v.z, v.w);
}

// ===========================================================================
// Tensor-core GEMM v8: fat-warp ILP (64x64 warp tile, 128 threads) + BK=64
// (stage = 4 proven 9216B subtiles), NSTAGE=3, 2 CTAs/SM.
// ===========================================================================
#define PROWB  144
#define TILEB  (64 * PROWB)                // 9216 B subtile: 128 rows x 32 k
#define STAGEB (4 * TILEB)                 // 36864 B: A-k0, A-k1, B-k0, B-k1
#define NSTAGE 3
#define GEMM_SMEM (NSTAGE * STAGEB)        // 110592 B (epilogue 67584 fits)
#define ROWOFF(r) (((r) & 63) * PROWB + ((r) >> 6) * 64)

template <bool BIAS, bool RELU, bool OUTHALF>
__global__ void __launch_bounds__(128, 2)
tc_gemm(const h16* __restrict__ A_g, const h16* __restrict__ B_g,
        const float* __restrict__ bias, float* __restrict__ C,
        h16* __restrict__ Ch, int M, int N, int K)
{
    extern __shared__ char smem[];
    const int tid  = threadIdx.x;
    const int wid  = tid >> 5;
    const int lane = tid & 31;
    const int g    = lane >> 2;
    const int t    = lane & 3;
    const int wm   = wid & 1;      // M half (64)
    const int wn   = wid >> 1;     // N half (64)
    const int m0   = blockIdx.y * 128;
    const int n0   = blockIdx.x * 128;

    const uint32_t smem0 = smem_u32(smem);

    const int arow_l = (lane & 7) + ((lane >> 3) & 1) * 8;
    const uint32_t aoffL =
        (uint32_t)(arow_l * PROWB + wm * 64 + (lane >> 4) * 16);
    const int brow_l = ((lane >> 4) & 1) * 8 + (lane & 7);
    const uint32_t boffL =
        (uint32_t)(brow_l * PROWB + wn * 64 + ((lane >> 3) & 1) * 16);

    float acc[4][8][4];
#pragma unroll
    for (int i = 0; i < 4; i++)
#pragma unroll
        for (int j = 0; j < 8; j++)
#pragma unroll
            for (int c = 0; c < 4; c++) acc[i][j][c] = 0.f;

    const int S = K >> 6;   // BK = 64

    // per stage: 2 tensors x 128 rows x 8 chunks(16B) = 2048 -> 16 per thread
    auto cp_stage = [&](int s, int b) {
        const int k0 = s << 6;
        char* base = smem + b * STAGEB;
#pragma unroll
        for (int i = 0; i < 16; i++) {
            const int sel   = i >> 3;                    // 0:A, 1:B
            const int inner = tid + (i & 7) * 128;       // 0..1023
            const int r     = inner >> 3;                // 0..127
            const int c     = inner & 7;                 // 16B chunks across 64 k
            const int kh    = c >> 2;                    // k-half subtile
            const int c4    = c & 3;
            const h16* src = (sel ? B_g : A_g) +
                             (size_t)((sel ? n0 : m0) + r) * K + k0 + kh * 32 + c4 * 8;
            uint32_t dst = smem_u32(base + (sel * 2 + kh) * TILEB +
                                    ROWOFF(r) + c4 * 16);
            CP_ASYNC16(dst, src);
        }
    };

    auto compute = [&](int b) {
        const uint32_t base = smem0 + b * STAGEB;
#pragma unroll
        for (int sub = 0; sub < 2; sub++) {
            const uint32_t Aa = base + sub * TILEB + aoffL;
            const uint32_t Bb = base + (2 + sub) * TILEB + boffL;
            uint32_t af[2][4][4], bf[2][4][4];
            // preload both k16 halves of this subtile up front (ILP)
#pragma unroll
            for (int ks = 0; ks < 2; ks++) {
#pragma unroll
                for (int mt = 0; mt < 4; mt++)
                    LDSM_X4(af[ks][mt], Aa + mt * (16 * PROWB) + ks * 32);
#pragma unroll
                for (int j = 0; j < 4; j++)
                    LDSM_X4(bf[ks][j], Bb + j * (16 * PROWB) + ks * 32);
            }
#pragma unroll
            for (int ks = 0; ks < 2; ks++)
#pragma unroll
                for (int mt = 0; mt < 4; mt++)
#pragma unroll
                    for (int nt = 0; nt < 8; nt++)
                        mma_f16(acc[mt][nt], af[ks][mt], &bf[ks][nt >> 1][(nt & 1) * 2]);
        }
    };

    // ---- 3-stage pipeline ----
    cp_stage(0, 0); CP_COMMIT();
    if (S > 1) { cp_stage(1, 1); CP_COMMIT(); }

    for (int s = 0; s < S; s++) {
        if (s + 1 < S) CP_WAIT1();
        else           CP_WAIT0();
        __syncthreads();
        if (s + 2 < S) { cp_stage(s + 2, (s + 2) % NSTAGE); CP_COMMIT(); }
        compute(s % NSTAGE);
    }
    __syncthreads();

    // ---- epilogue: regs -> smem -> coalesced out ----
    float* stage = reinterpret_cast<float*>(smem);   // 128 x pitch 132
#pragma unroll
    for (int mt = 0; mt < 4; mt++) {
#pragma unroll
        for (int nt = 0; nt < 8; nt++) {
            int row = wm * 64 + mt * 16 + g;
            int col = wn * 64 + nt * 8 + t * 2;
            *reinterpret_cast<float2*>(&stage[row * 132 + col]) =
                make_float2(acc[mt][nt][0], acc[mt][nt][1]);
            *reinterpret_cast<float2*>(&stage[(row + 8) * 132 + col]) =
                make_float2(acc[mt][nt][2], acc[mt][nt][3]);
        }
    }
    __syncthreads();

#pragma unroll
    for (int i = 0; i < 32; i++) {
        int f   = i * 128 + tid;
        int row = f >> 5;
        int c4  = f & 31;
        float4 v = *reinterpret_cast<float4*>(&stage[row * 132 + c4 * 4]);
        if (BIAS) {
            float4 bv = *reinterpret_cast<const float4*>(bias + n0 + c4 * 4);
            v.x += bv.x; v.y += bv.y; v.z += bv.z; v.w += bv.w;
        }
        if (RELU) {
            v.x = fmaxf(v.x, 0.f); v.y = fmaxf(v.y, 0.f);
            v.z = fmaxf(v.z, 0.f); v.w = fmaxf(v.w, 0.f);
        }
        size_t oidx = (size_t)(m0 + row) * N + n0 + c4 * 4;
        if (OUTHALF) {
            *reinterpret_cast<__half2*>(Ch + oidx)     = __floats2half2_rn(v.x, v.y);
            *reinterpret_cast<__half2*>(Ch + oidx + 2) = __floats2half2_rn(v.z, v.w);
        } else {
            *reinterpret_cast<float4*>(C + oidx) = v;
        }
    }
}

// ===========================================================================
// Flash attention via mma.sync (R13/R14-proven, strided Q/KV)
// ===========================================================================
#define AT_PITCH 72

template <bool CAUSAL>
__global__ void __launch_bounds__(128)
attn_kernel(const h16* __restrict__ Qh, const h16* __restrict__ Kh,
            const h16* __restrict__ Vh, h16* __restrict__ Oh,
            int Lk, int qstr, int kvstr)
{
    __shared__ h16 sQ[64 * AT_PITCH];
    __shared__ h16 sK[3][32 * AT_PITCH];
    __shared__ h16 sV[3][32 * AT_PITCH];

    const int b    = blockIdx.z;
    const int h    = blockIdx.y;
    const int q0   = blockIdx.x * 64;
    const int tid  = threadIdx.x;
    const int lane = tid & 31;
    const int w    = tid >> 5;
    const int wr0  = w * 16;
    const int g    = lane >> 2;
    const int t    = lane & 3;

    const int nkt = CAUSAL ? ((q0 + 64) >> 5) : (Lk >> 5);

    auto cp_q = [&]() {
#pragma unroll
        for (int i = 0; i < 4; i++) {
            int idx = tid + i * 128;
            int r = idx >> 3, c = idx & 7;
            const h16* src = Qh + (size_t)(b * Sc + q0 + r) * qstr + h * 64 + c * 8;
            CP_ASYNC16(smem_u32(&sQ[r * AT_PITCH]) + c * 16, src);
        }
    };
    auto cp_kv = [&](int kt, int stg) {
        const int k0 = kt << 5;
#pragma unroll
        for (int i = 0; i < 4; i++) {
            int idx = tid + i * 128;
            int sel = idx >> 8;
            int rem = idx & 255;
            int r = rem >> 3, c = rem & 7;
            const h16* src = (sel ? Vh : Kh) +
                             (size_t)(b * Lk + k0 + r) * kvstr + h * 64 + c * 8;
            h16* dst = (sel ? sV[stg] : sK[stg]) + r * AT_PITCH;
            CP_ASYNC16(smem_u32(dst) + c * 16, src);
        }
    };

    cp_q();
    CP_COMMIT();
    cp_kv(0, 0);
    CP_COMMIT();
    if (nkt > 1) { cp_kv(1, 1); CP_COMMIT(); }
    if (nkt > 1) CP_WAIT2(); else CP_WAIT1();
    __syncthreads();

    uint32_t aq[4][4];
    {
        const int qrow = (lane & 7) + ((lane >> 3) & 1) * 8;
        const uint32_t qaddr = smem_u32(sQ) +
            (uint32_t)((wr0 + qrow) * (AT_PITCH * 2) + (lane >> 4) * 16);
#pragma unroll
        for (int ks = 0; ks < 4; ks++)
            LDSM_X4(aq[ks], qaddr + ks * 32);
    }

    const int kb_row = ((lane >> 4) & 1) * 8 + (lane & 7);
    const uint32_t kboff = (uint32_t)(kb_row * (AT_PITCH * 2) + ((lane >> 3) & 1) * 16);
    const int v_row = ((lane >> 3) & 1) * 8 + (lane & 7);
    const uint32_t vboff = (uint32_t)(v_row * (AT_PITCH * 2) + (lane >> 4) * 16);

    float oacc[8][4];
#pragma unroll
    for (int d = 0; d < 8; d++)
#pragma unroll
        for (int c = 0; c < 4; c++) oacc[d][c] = 0.f;
    float mrow0 = -1e30f, mrow1 = -1e30f, lrow0 = 0.f, lrow1 = 0.f;

    const int row0 = q0 + wr0 + g;
    const int row1 = row0 + 8;

    for (int kt = 0; kt < nkt; kt++) {
        if (kt + 1 < nkt) CP_WAIT1();
        else              CP_WAIT0();
        __syncthreads();
        if (kt + 2 < nkt) { cp_kv(kt + 2, (kt + 2) % 3); CP_COMMIT(); }

        const int stg = kt % 3;
        const int k0  = kt << 5;

        float s[4][4];
#pragma unroll
        for (int nt = 0; nt < 4; nt++)
#pragma unroll
            for (int c = 0; c < 4; c++) s[nt][c] = 0.f;
        const uint32_t Kb = smem_u32(sK[stg]) + kboff;
#pragma unroll
        for (int ks = 0; ks < 4; ks++) {
            uint32_t bk[2][4];
#pragma unroll
            for (int j = 0; j < 2; j++)
                LDSM_X4(bk[j], Kb + j * (16 * AT_PITCH * 2) + ks * 32);
#pragma unroll
            for (int nt = 0; nt < 4; nt++)
                mma_f16(s[nt], aq[ks], &bk[nt >> 1][(nt & 1) * 2]);
        }

#pragma unroll
        for (int nt = 0; nt < 4; nt++) {
            const int col0 = k0 + nt * 8 + 2 * t;
#pragma unroll
            for (int c = 0; c < 4; c++) s[nt][c] *= 0.125f;
            if (CAUSAL) {
                if (col0     > row0) s[nt][0] = -1e9f;
                if (col0 + 1 > row0) s[nt][1] = -1e9f;
                if (col0     > row1) s[nt][2] = -1e9f;
                if (col0 + 1 > row1) s[nt][3] = -1e9f;
            }
        }

        float ml0 = -1e30f, ml1 = -1e30f;
#pragma unroll
        for (int nt = 0; nt < 4; nt++) {
            ml0 = fmaxf(ml0, fmaxf(s[nt][0], s[nt][1]));
            ml1 = fmaxf(ml1, fmaxf(s[nt][2], s[nt][3]));
        }
        ml0 = fmaxf(ml0, __shfl_xor_sync(0xffffffffu, ml0, 1));
        ml0 = fmaxf(ml0, __shfl_xor_sync(0xffffffffu, ml0, 2));
        ml1 = fmaxf(ml1, __shfl_xor_sync(0xffffffffu, ml1, 1));
        ml1 = fmaxf(ml1, __shfl_xor_sync(0xffffffffu, ml1, 2));
        const float mn0 = fmaxf(mrow0, ml0);
        const float mn1 = fmaxf(mrow1, ml1);
        const float al0 = __expf(mrow0 - mn0);
        const float al1 = __expf(mrow1 - mn1);
        mrow0 = mn0; mrow1 = mn1;

        uint32_t pa[4][2];
        float ls0 = 0.f, ls1 = 0.f;
#pragma unroll
        for (int nt = 0; nt < 4; nt++) {
            float p0 = __expf(s[nt][0] - mn0);
            float p1 = __expf(s[nt][1] - mn0);
            float p2 = __expf(s[nt][2] - mn1);
            float p3 = __expf(s[nt][3] - mn1);
            ls0 += p0 + p1;
            ls1 += p2 + p3;
            __half2 h01 = __floats2half2_rn(p0, p1);
            __half2 h23 = __floats2half2_rn(p2, p3);
            pa[nt][0] = *reinterpret_cast<uint32_t*>(&h01);
            pa[nt][1] = *reinterpret_cast<uint32_t*>(&h23);
        }
        ls0 += __shfl_xor_sync(0xffffffffu, ls0, 1);
        ls0 += __shfl_xor_sync(0xffffffffu, ls0, 2);
        ls1 += __shfl_xor_sync(0xffffffffu, ls1, 1);
        ls1 += __shfl_xor_sync(0xffffffffu, ls1, 2);
        lrow0 = lrow0 * al0 + ls0;
        lrow1 = lrow1 * al1 + ls1;
#pragma unroll
        for (int d = 0; d < 8; d++) {
            oacc[d][0] *= al0; oacc[d][1] *= al0;
            oacc[d][2] *= al1; oacc[d][3] *= al1;
        }

        const uint32_t Vb = smem_u32(sV[stg]) + vboff;
#pragma unroll
        for (int ks2 = 0; ks2 < 2; ks2++) {
            uint32_t aP[4] = { pa[2 * ks2][0], pa[2 * ks2][1],
                               pa[2 * ks2 + 1][0], pa[2 * ks2 + 1][1] };
#pragma unroll
            for (int dp = 0; dp < 4; dp++) {
                uint32_t bv[4];
                LDSM_X4T(bv, Vb + ks2 * (16 * AT_PITCH * 2) + dp * 32);
                mma_f16(oacc[dp * 2 + 0], aP, &bv[0]);
                mma_f16(oacc[dp * 2 + 1], aP, &bv[2]);
            }
        }
    }

    const float inv0 = 1.f / lrow0;
    const float inv1 = 1.f / lrow1;
    h16* o0p = Oh + (size_t)(b * Sc + row0) * Dc + h * 64;
    h16* o1p = Oh + (size_t)(b * Sc + row1) * Dc + h * 64;
#pragma unroll
    for (int d = 0; d < 8; d++) {
        int col = d * 8 + 2 * t;
        *reinterpret_cast<__half2*>(o0p + col) =
            __floats2half2_rn(oacc[d][0] * inv0, oacc[d][1] * inv0);
        *reinterpret_cast<__half2*>(o1p + col) =
            __floats2half2_rn(oacc[d][2] * inv1, oacc[d][3] * inv1);
    }
}

// ---------------------------------------------------------------------------
// Residual + LayerNorm; writes fp32 + fp16 mirror
// ---------------------------------------------------------------------------
__global__ void __launch_bounds__(256)
ln_kernel(const float* __restrict__ x, const float* __restrict__ add,
          const float* __restrict__ s, const float* __restrict__ b,
          float* __restrict__ out, h16* __restrict__ oh)
{
    const int row = blockIdx.x;
    const int tid = threadIdx.x;
    const size_t base = (size_t)row * Dc;

    float v[4];
    float sum = 0.f, sq = 0.f;
#pragma unroll
    for (int i = 0; i < 4; i++) {
        int c = tid + i * 256;
        float val = x[base + c];
        if (add) val += add[base + c];
        v[i] = val;
        sum += val;
        sq  += val * val;
    }
#pragma unroll
    for (int off = 16; off > 0; off >>= 1) {
        sum += __shfl_xor_sync(0xffffffffu, sum, off);
        sq  += __shfl_xor_sync(0xffffffffu, sq, off);
    }
    __shared__ float s1[8], s2[8];
    __shared__ float mu_s, inv_s;
    int lane = tid & 31, wid = tid >> 5;
    if (lane == 0) { s1[wid] = sum; s2[wid] = sq; }
    __syncthreads();
    if (tid == 0) {
        float ts = 0.f, tq = 0.f;
#pragma unroll
        for (int i = 0; i < 8; i++) { ts += s1[i]; tq += s2[i]; }
        float mu  = ts * (1.f / Dc);
        float var = tq * (1.f / Dc) - mu * mu;
        mu_s  = mu;
        inv_s = rsqrtf(var + 1e-5f);
    }
    __syncthreads();
    float mu = mu_s, inv = inv_s;
#pragma unroll
    for (int i = 0; i < 4; i++) {
        int c = tid + i * 256;
        float r = (v[i] - mu) * inv * s[c] + b[c];
        out[base + c] = r;
        oh[base + c]  = __float2half(r);
    }
}

// ---------------------------------------------------------------------------
// Embedding gather + positional add; writes fp32 + fp16
// ---------------------------------------------------------------------------
__global__ void __launch_bounds__(256)
embed_kernel(const int* __restrict__ seq, const float* __restrict__ emb,
             const float* __restrict__ pos, float* __restrict__ x,
             h16* __restrict__ xh)
{
    const int row  = blockIdx.x;
    const int sidx = row & (Sc - 1);
    const int tok  = seq[row];
    const int tid  = threadIdx.x;
#pragma unroll
    for (int i = 0; i < 4; i++) {
        int c = tid + i * 256;
        float r = emb[(size_t)tok * Dc + c] + pos[(size_t)sidx * Dc + c];
        size_t o = (size_t)row * Dc + c;
        x[o]  = r;
        xh[o] = __float2half(r);
    }
}

// ---------------------------------------------------------------------------
// Host orchestration
// ---------------------------------------------------------------------------
template <bool BIAS, bool RELU, bool OUTHALF>
static void launch_gemm(const h16* a, const h16* b, const float* bias,
                        float* C, h16* ch, int M, int N, int K)
{
    cudaFuncSetAttribute(tc_gemm<BIAS, RELU, OUTHALF>,
                         cudaFuncAttributeMaxDynamicSharedMemorySize, GEMM_SMEM);
    dim3 grid(N / 128, M / 128);
    tc_gemm<BIAS, RELU, OUTHALF><<<grid, 128, GEMM_SMEM>>>(a, b, bias, C, ch, M, N, K);
}

extern "C" void kernel_launch(void* const* d_in, const int* in_sizes, int n_in,
                              void* d_out, int out_size)
{
    (void)in_sizes; (void)n_in; (void)out_size;

    const float* encoded      = (const float*)d_in[0];
    const int*   seq          = (const int*)  d_in[1];
    const float* input_embed  = (const float*)d_in[2];
    const float* output_embed = (const float*)d_in[3];
    const float* output_bias  = (const float*)d_in[4];
    const float* pos_embed    = (const float*)d_in[5];
    const float* Wq  = (const float*)d_in[6];
    const float* Wk  = (const float*)d_in[7];
    const float* Wv  = (const float*)d_in[8];
    const float* Wo  = (const float*)d_in[9];
    const float* Wqc = (const float*)d_in[10];
    const float* Wkc = (const float*)d_in[11];
    const float* Wvc = (const float*)d_in[12];
    const float* Woc = (const float*)d_in[13];
    const float* W1  = (const float*)d_in[14];
    const float* b1  = (const float*)d_in[15];
    const float* W2  = (const float*)d_in[16];
    const float* b2  = (const float*)d_in[17];
    const float* ln1s = (const float*)d_in[18];
    const float* ln1b = (const float*)d_in[19];
    const float* ln2s = (const float*)d_in[20];
    const float* ln2b = (const float*)d_in[21];
    const float* ln3s = (const float*)d_in[22];
    const float* ln3b = (const float*)d_in[23];
    const float* lnfs = (const float*)d_in[24];
    const float* lnfb = (const float*)d_in[25];

    float *x, *o;
    cudaGetSymbolAddress((void**)&x, g_x);
    cudaGetSymbolAddress((void**)&o, g_o);
    h16 *w, *xh, *qkvh, *qh, *kvh, *ah, *fh, *eh;
    cudaGetSymbolAddress((void**)&w,    g_w);
    cudaGetSymbolAddress((void**)&xh,   g_xh);
    cudaGetSymbolAddress((void**)&qkvh, g_qkvh);
    cudaGetSymbolAddress((void**)&qh,   g_qh);
    cudaGetSymbolAddress((void**)&kvh,  g_kvh);
    cudaGetSymbolAddress((void**)&ah,   g_ah);
    cudaGetSymbolAddress((void**)&fh,   g_fh);
    cudaGetSymbolAddress((void**)&eh,   g_eh);

    // ---- conversions: 2 launches ----
    convT_all<<<dim3(4096, 1, 60), dim3(32, 8)>>>(Wq, Wk, Wv, Wo, Wqc, Wkc, Wvc, Woc,
                                                  W1, W2, w);
    conv_all<<<dim3(Vc, 1, 2), 256>>>((const float4*)output_embed, (const float4*)encoded,
                                      (__half2*)(w + EOFF), (__half2*)eh);

    const int NR  = Bc * Sc;   // 4096
    const int NRE = Bc * Mc;   // 8192

    embed_kernel<<<NR, 256>>>(seq, input_embed, pos_embed, x, xh);

    const dim3 agrid(Sc / 64, Hc, Bc);   // (8, 16, 8)

    for (int i = 0; i < Lc; i++) {
        const size_t lb = (size_t)i * WOFF_LAYER;
        const h16* wl = w + lb;

        // ---- self attention: fused QKV ----
        launch_gemm<false, false, true>(xh, wl, nullptr, nullptr, qkvh, NR, 3 * Dc, Dc);
        attn_kernel<true><<<agrid, 128>>>(qkvh, qkvh + Dc, qkvh + 2 * Dc, ah,
                                          Sc, 3 * Dc, 3 * Dc);
        launch_gemm<false, false, false>(ah, wl + 3 * 1048576, nullptr, o, nullptr, NR, Dc, Dc);
        ln_kernel<<<NR, 256>>>(x, o, ln1s + (size_t)i * Dc, ln1b + (size_t)i * Dc, x, xh);

        // ---- cross attention: Q alone; fused KV ----
        launch_gemm<false, false, true>(xh, wl + 4 * 1048576, nullptr, nullptr, qh, NR, Dc, Dc);
        launch_gemm<false, false, true>(eh, wl + 5 * 1048576, nullptr, nullptr, kvh,
                                        NRE, 2 * Dc, Dc);
        attn_kernel<false><<<agrid, 128>>>(qh, kvh, kvh + Dc, ah, Mc, Dc, 2 * Dc);
        launch_gemm<false, false, false>(ah, wl + 7 * 1048576, nullptr, o, nullptr, NR, Dc, Dc);
        ln_kernel<<<NR, 256>>>(x, o, ln2s + (size_t)i * Dc, ln2b + (size_t)i * Dc, x, xh);

        // ---- FFN ----
        launch_gemm<true, true, true>(xh, wl + WOFF_W1, b1 + (size_t)i * DFc,
                                      nullptr, fh, NR, DFc, Dc);
        launch_gemm<true, false, false>(fh, wl + WOFF_W2, b2 + (size_t)i * Dc,
                                        o, nullptr, NR, Dc, DFc);
        ln_kernel<<<NR, 256>>>(x, o, ln3s + (size_t)i * Dc, ln3b + (size_t)i * Dc, x, xh);
    }

    // final norm + logits
    ln_kernel<<<NR, 256>>>(x, nullptr, lnfs, lnfb, x, xh);
    launch_gemm<true, false, false>(xh, w + EOFF, output_bias, (float*)d_out, nullptr,
                                    NR, Vc, Dc);
}